// round 4
// baseline (speedup 1.0000x reference)
#include <cuda_runtime.h>
#include <cstdint>

// Hierarchical polarization, fully restructured:
//   P_0 = pairwise means of Z;  P_{L+1}[G] = mean over pair of (P_L + At_L)
//   out = Z + sum_L At_L[group(s,L)]
// pyramid_kernel: levels 0..6 fused per 128-Z-row block (1024 blocks).
// tail_kernel:    levels 7..13 fused per batch (8 blocks).
// final_kernel:   flat gather over the At pyramid.

typedef unsigned long long u64;

__device__ float4 g_At4[8388096];     // At pyramid, 14 levels, 128 MiB
__device__ float  g_P6u[1024 * 256];  // updated level-6 rows (input to level 7)

__device__ __forceinline__ u64 pack2(float lo, float hi) {
    u64 r; asm("mov.b64 %0, {%1, %2};" : "=l"(r) : "f"(lo), "f"(hi)); return r;
}
__device__ __forceinline__ void unpack2(u64 v, float& lo, float& hi) {
    asm("mov.b64 {%0, %1}, %2;" : "=f"(lo), "=f"(hi) : "l"(v));
}
__device__ __forceinline__ u64 ffma2(u64 a, u64 b, u64 c) {
    u64 d; asm("fma.rn.f32x2 %0, %1, %2, %3;" : "=l"(d) : "l"(a), "l"(b), "l"(c)); return d;
}
__device__ __forceinline__ u64 fadd2(u64 a, u64 b) {
    u64 d; asm("add.rn.f32x2 %0, %1, %2;" : "=l"(d) : "l"(a), "l"(b)); return d;
}

__device__ __forceinline__ float gelu_tanh(float x) {
    // jax.nn.gelu approximate=True; tanh(u) = 1 - 2/(exp(2u)+1)
    float u = 0.7978845608028654f * (x + 0.044715f * x * x * x);
    float e = __expf(2.0f * u);
    float t = 1.0f - __fdividef(2.0f, e + 1.0f);
    return 0.5f * x * (1.0f + t);
}

__device__ __forceinline__ long long offF(int l) {   // float offset of level l in At pyramid
    return (131072LL - (131072LL >> l)) * 256LL;
}

// ---------------------------------------------------------------------------
// One MLP level over np row-pairs held pair-interleaved in Xc (u64 per (pair,d)).
// Each warp handles CP pairs per chunk. Produces At rows (global) and the
// next level's pair-interleaved rows in Xn (pair means of x+At), computed
// entirely in registers.
// ---------------------------------------------------------------------------
template<int CP>
__device__ __forceinline__ void mlp_level(
    const u64* __restrict__ Xc, u64* __restrict__ Xn, u64* __restrict__ Hs,
    int np, float* __restrict__ AtR,
    const float* __restrict__ w1, const float* __restrict__ b1v,
    const float* __restrict__ w2, const float* __restrict__ b2v,
    int wp, int lane)
{
    for (int pb = CP * wp; pb < np; pb += CP * 8) {
        // ---- phase 1: H = gelu(X @ W1 + b1), f32x2, 2 chains per pair ----
        u64 acc0[CP], acc1[CP];
        #pragma unroll
        for (int c = 0; c < CP; c++) { acc0[c] = 0ULL; acc1[c] = 0ULL; }
        const float* w1l = w1 + lane;
        #pragma unroll 4
        for (int d = 0; d < 256; d += 2) {
            float wa = w1l[d * 32];
            float wb = w1l[d * 32 + 32];
            u64 wA = pack2(wa, wa), wB = pack2(wb, wb);
            #pragma unroll
            for (int c = 0; c < CP; c++) {
                const u64* xp = Xc + (pb + c) * 256;
                acc0[c] = ffma2(xp[d],     wA, acc0[c]);   // LDS.128 pairs with next
                acc1[c] = ffma2(xp[d + 1], wB, acc1[c]);
            }
        }
        float bb = b1v[lane];
        #pragma unroll
        for (int c = 0; c < CP; c++) {
            float lo, hi;
            unpack2(fadd2(acc0[c], acc1[c]), lo, hi);
            Hs[(wp * 4 + c) * 32 + lane] = pack2(gelu_tanh(lo + bb), gelu_tanh(hi + bb));
        }
        __syncwarp();

        // ---- phase 3: At = H @ W2 + b2; write At; next-level means in regs ----
        #pragma unroll
        for (int k = 0; k < 8; k++) {
            int d = lane + 32 * k;
            float bv = b2v[d];
            u64 acc[CP];
            #pragma unroll
            for (int c = 0; c < CP; c++) acc[c] = pack2(bv, bv);
            #pragma unroll 4
            for (int j = 0; j < 32; j += 2) {
                float wa = w2[j * 256 + d], wb = w2[(j + 1) * 256 + d];
                u64 wA = pack2(wa, wa), wB = pack2(wb, wb);
                #pragma unroll
                for (int c = 0; c < CP; c++) {
                    const u64* hp = Hs + (wp * 4 + c) * 32;
                    acc[c] = ffma2(hp[j],     wA, acc[c]);
                    acc[c] = ffma2(hp[j + 1], wB, acc[c]);
                }
            }
            float mean[CP];
            #pragma unroll
            for (int c = 0; c < CP; c++) {
                float aL, aH; unpack2(acc[c], aL, aH);
                int r2 = 2 * (pb + c);
                AtR[r2 * 256 + d]       = aL;
                AtR[(r2 + 1) * 256 + d] = aH;
                float uL, uH; unpack2(fadd2(Xc[(pb + c) * 256 + d], acc[c]), uL, uH);
                mean[c] = 0.5f * (uL + uH);
            }
            if (CP == 4) {
                Xn[(pb >> 1) * 256 + d]       = pack2(mean[0], mean[1]);
                Xn[((pb >> 1) + 1) * 256 + d] = pack2(mean[2], mean[3]);
            } else if (CP == 2) {
                Xn[(pb >> 1) * 256 + d] = pack2(mean[0], mean[1]);
            } else {
                ((float*)(Xn + (pb >> 1) * 256 + d))[pb & 1] = mean[0];
            }
        }
        __syncwarp();
    }
}

// Final single-row level (nr == 1). Row stored in even slots of Xc pair 0.
// uOut != nullptr -> also write the updated row (x + At).
__device__ __forceinline__ void mlp_final_row(
    const u64* __restrict__ Xc, float* __restrict__ Hf,
    float* __restrict__ AtR, float* __restrict__ uOut,
    const float* __restrict__ w1, const float* __restrict__ b1v,
    const float* __restrict__ w2, const float* __restrict__ b2v,
    int wp, int lane)
{
    if (wp != 0) return;
    const float* xf = (const float*)Xc;        // x[d] = xf[2d]
    float a0 = 0.f, a1 = 0.f, a2 = 0.f, a3 = 0.f;
    #pragma unroll 4
    for (int d = 0; d < 256; d += 4) {
        a0 = fmaf(xf[2 * d + 0], w1[(d + 0) * 32 + lane], a0);
        a1 = fmaf(xf[2 * d + 2], w1[(d + 1) * 32 + lane], a1);
        a2 = fmaf(xf[2 * d + 4], w1[(d + 2) * 32 + lane], a2);
        a3 = fmaf(xf[2 * d + 6], w1[(d + 3) * 32 + lane], a3);
    }
    Hf[lane] = gelu_tanh((a0 + a1) + (a2 + a3) + b1v[lane]);
    __syncwarp();
    #pragma unroll
    for (int k = 0; k < 8; k++) {
        int d = lane + 32 * k;
        float s0 = b2v[d], s1 = 0.f;
        #pragma unroll 8
        for (int j = 0; j < 32; j += 2) {
            s0 = fmaf(Hf[j],     w2[j * 256 + d],       s0);
            s1 = fmaf(Hf[j + 1], w2[(j + 1) * 256 + d], s1);
        }
        float a = s0 + s1;
        AtR[d] = a;
        if (uOut) uOut[d] = xf[2 * d] + a;
    }
}

// ---------------------------------------------------------------------------
// Levels 0..6 fused. Block = 128 Z rows = 32 level-0 pairs. 1024 blocks.
// smem: region A 32 pairs (64KB) + region B 16 pairs (32KB) + H (8KB) = 104KB.
// ---------------------------------------------------------------------------
__global__ void __launch_bounds__(256, 2) pyramid_kernel(
    const float2* __restrict__ Z2,
    const float* __restrict__ W1, const float* __restrict__ b1,
    const float* __restrict__ W2, const float* __restrict__ b2)
{
    extern __shared__ u64 sh[];
    u64* A  = sh;            // 32*256 u64
    u64* B  = sh + 8192;     // 16*256 u64
    u64* Hs = sh + 12288;    // 32*32 u64

    const int t    = threadIdx.x;
    const int lane = t & 31;
    const int wp   = t >> 5;

    // ---- fill A: pair p <-> Z rows 4p..4p+3 (pair means), pair-interleaved ----
    {
        const long long zr0 = (long long)blockIdx.x * 128;
        #pragma unroll
        for (int k = 0; k < 16; k++) {
            int task = t + 256 * k;            // 0..4095
            int pr   = task >> 7;              // 0..31
            int dh   = task & 127;             // d/2
            const float2* zp = Z2 + (zr0 + 4 * pr) * 128 + dh;
            float2 a0 = zp[0], a1 = zp[128], a2 = zp[256], a3 = zp[384];
            ((float4*)A)[pr * 128 + dh] =
                make_float4(0.5f * (a0.x + a1.x), 0.5f * (a2.x + a3.x),
                            0.5f * (a0.y + a1.y), 0.5f * (a2.y + a3.y));
        }
    }
    __syncthreads();

    float* AtBase = (float*)g_At4;
    const long long p0base = (long long)blockIdx.x * 64;  // global level-0 row base

    u64* Xc = A; u64* Xn = B;
    int np = 32;
    for (int lvl = 0; lvl < 6; lvl++) {
        const float* w1 = W1 + lvl * 8192;
        const float* v1 = b1 + lvl * 32;
        const float* w2 = W2 + lvl * 8192;
        const float* v2 = b2 + lvl * 256;
        float* AtR = AtBase + offF(lvl) + (p0base >> lvl) * 256;
        if (np == 32)      mlp_level<4>(Xc, Xn, Hs, np, AtR, w1, v1, w2, v2, wp, lane);
        else if (np == 16) mlp_level<2>(Xc, Xn, Hs, np, AtR, w1, v1, w2, v2, wp, lane);
        else               mlp_level<1>(Xc, Xn, Hs, np, AtR, w1, v1, w2, v2, wp, lane);
        __syncthreads();
        u64* tmp = Xc; Xc = Xn; Xn = tmp;
        np >>= 1;
    }
    // level 6: single row
    mlp_final_row(Xc, (float*)Hs,
                  AtBase + offF(6) + (p0base >> 6) * 256,
                  g_P6u + (p0base >> 6) * 256,
                  W1 + 6 * 8192, b1 + 6 * 32, W2 + 6 * 8192, b2 + 6 * 256,
                  wp, lane);
}

// ---------------------------------------------------------------------------
// Levels 7..13 fused. One block per batch. Input: 128 updated level-6 rows.
// ---------------------------------------------------------------------------
__global__ void __launch_bounds__(256, 2) tail_kernel(
    const float* __restrict__ W1, const float* __restrict__ b1,
    const float* __restrict__ W2, const float* __restrict__ b2)
{
    extern __shared__ u64 sh[];
    u64* A  = sh;
    u64* B  = sh + 8192;
    u64* Hs = sh + 12288;

    const int b    = blockIdx.x;
    const int t    = threadIdx.x;
    const int lane = t & 31;
    const int wp   = t >> 5;

    // fill A: level-7 pair p <-> P6u rows b*128 + 4p..4p+3 (pair means)
    {
        const float2* P2 = (const float2*)g_P6u;
        #pragma unroll
        for (int k = 0; k < 16; k++) {
            int task = t + 256 * k;
            int pr   = task >> 7;
            int dh   = task & 127;
            const float2* zp = P2 + (long long)(b * 128 + 4 * pr) * 128 + dh;
            float2 a0 = zp[0], a1 = zp[128], a2 = zp[256], a3 = zp[384];
            ((float4*)A)[pr * 128 + dh] =
                make_float4(0.5f * (a0.x + a1.x), 0.5f * (a2.x + a3.x),
                            0.5f * (a0.y + a1.y), 0.5f * (a2.y + a3.y));
        }
    }
    __syncthreads();

    float* AtBase = (float*)g_At4;

    u64* Xc = A; u64* Xn = B;
    int np = 32;
    for (int i = 0; i < 6; i++) {
        int lvl = 7 + i;
        int tt  = (lvl < 10) ? lvl : 9;
        const float* w1 = W1 + tt * 8192;
        const float* v1 = b1 + tt * 32;
        const float* w2 = W2 + tt * 8192;
        const float* v2 = b2 + tt * 256;
        float* AtR = AtBase + offF(lvl) + (long long)b * (64 >> i) * 256;
        if (np == 32)      mlp_level<4>(Xc, Xn, Hs, np, AtR, w1, v1, w2, v2, wp, lane);
        else if (np == 16) mlp_level<2>(Xc, Xn, Hs, np, AtR, w1, v1, w2, v2, wp, lane);
        else               mlp_level<1>(Xc, Xn, Hs, np, AtR, w1, v1, w2, v2, wp, lane);
        __syncthreads();
        u64* tmp = Xc; Xc = Xn; Xn = tmp;
        np >>= 1;
    }
    // level 13: single row per batch, no u output
    mlp_final_row(Xc, (float*)Hs,
                  AtBase + offF(13) + b * 256, nullptr,
                  W1 + 9 * 8192, b1 + 9 * 32, W2 + 9 * 8192, b2 + 9 * 256,
                  wp, lane);
}

// ---------------------------------------------------------------------------
// out = Z + sum over 14 levels of At[level][b, s>>(L+1), d]
// ---------------------------------------------------------------------------
__global__ void __launch_bounds__(256) final_kernel(
    const float4* __restrict__ Z4, float4* __restrict__ out4)
{
    int i   = blockIdx.x * 256 + threadIdx.x;
    int d4  = i & 63;
    int row = i >> 6;
    int b   = row >> 14;
    int s   = row & 16383;

    float4 acc = Z4[i];
    long long off4 = 0;
    int ng = 8192;
    #pragma unroll
    for (int L = 0; L < 14; L++) {
        int g = s >> (L + 1);
        float4 a = g_At4[off4 + (long long)(b * ng + g) * 64 + d4];
        acc.x += a.x; acc.y += a.y; acc.z += a.z; acc.w += a.w;
        off4 += 512LL * ng;
        ng >>= 1;
    }
    out4[i] = acc;
}

extern "C" void kernel_launch(void* const* d_in, const int* in_sizes, int n_in,
                              void* d_out, int out_size)
{
    const float* Z  = (const float*)d_in[0];
    const float* W1 = (const float*)d_in[1];
    const float* b1 = (const float*)d_in[2];
    const float* W2 = (const float*)d_in[3];
    const float* b2 = (const float*)d_in[4];

    const int SMEM = (32 + 16) * 256 * 8 + 32 * 32 * 8;   // 106496 B
    static bool attrSet = false;
    if (!attrSet) {
        cudaFuncSetAttribute(pyramid_kernel, cudaFuncAttributeMaxDynamicSharedMemorySize, SMEM);
        cudaFuncSetAttribute(tail_kernel,    cudaFuncAttributeMaxDynamicSharedMemorySize, SMEM);
        attrSet = true;
    }

    pyramid_kernel<<<1024, 256, SMEM>>>((const float2*)Z, W1, b1, W2, b2);
    tail_kernel<<<8, 256, SMEM>>>(W1, b1, W2, b2);
    final_kernel<<<32768, 256>>>((const float4*)Z, (float4*)d_out);
}

// round 6
// speedup vs baseline: 1.0042x; 1.0042x over previous
#include <cuda_runtime.h>
#include <cstdint>

// Hierarchical polarization, fully restructured:
//   P_0 = pairwise means of Z;  P_{L+1}[G] = mean over pair of (P_L + At_L)
//   out = Z + sum_L At_L[group(s,L)]
// pyramid_kernel: levels 0..6 fused per 128-Z-row block (1024 blocks).
// tail_kernel:    levels 7..13 fused per batch (8 blocks).
// final_kernel:   flat gather over the At pyramid.

typedef unsigned long long u64;

__device__ float4 g_At4[8388096];     // At pyramid, 14 levels, 128 MiB
__device__ float  g_P6u[1024 * 256];  // updated level-6 rows (input to level 7)

__device__ __forceinline__ u64 pack2(float lo, float hi) {
    u64 r; asm("mov.b64 %0, {%1, %2};" : "=l"(r) : "f"(lo), "f"(hi)); return r;
}
__device__ __forceinline__ void unpack2(u64 v, float& lo, float& hi) {
    asm("mov.b64 {%0, %1}, %2;" : "=f"(lo), "=f"(hi) : "l"(v));
}
__device__ __forceinline__ u64 ffma2(u64 a, u64 b, u64 c) {
    u64 d; asm("fma.rn.f32x2 %0, %1, %2, %3;" : "=l"(d) : "l"(a), "l"(b), "l"(c)); return d;
}
__device__ __forceinline__ u64 fadd2(u64 a, u64 b) {
    u64 d; asm("add.rn.f32x2 %0, %1, %2;" : "=l"(d) : "l"(a), "l"(b)); return d;
}

__device__ __forceinline__ float gelu_tanh(float x) {
    // jax.nn.gelu approximate=True; tanh(u) = 1 - 2/(exp(2u)+1)
    float u = 0.7978845608028654f * (x + 0.044715f * x * x * x);
    float e = __expf(2.0f * u);
    float t = 1.0f - __fdividef(2.0f, e + 1.0f);
    return 0.5f * x * (1.0f + t);
}

__device__ __forceinline__ long long offF(int l) {   // float offset of level l in At pyramid
    return (131072LL - (131072LL >> l)) * 256LL;
}

// ---------------------------------------------------------------------------
// One MLP level over np row-pairs held pair-interleaved in Xc (u64 per (pair,d)).
// Each warp handles CP pairs per chunk. Produces At rows (global) and the
// next level's pair-interleaved rows in Xn (pair means of x+At), computed
// entirely in registers.
// ---------------------------------------------------------------------------
template<int CP>
__device__ __forceinline__ void mlp_level(
    const u64* __restrict__ Xc, u64* __restrict__ Xn, u64* __restrict__ Hs,
    int np, float* __restrict__ AtR,
    const float* __restrict__ w1, const float* __restrict__ b1v,
    const float* __restrict__ w2, const float* __restrict__ b2v,
    int wp, int lane)
{
    for (int pb = CP * wp; pb < np; pb += CP * 8) {
        // ---- phase 1: H = gelu(X @ W1 + b1), f32x2, 2 chains per pair ----
        u64 acc0[CP], acc1[CP];
        #pragma unroll
        for (int c = 0; c < CP; c++) { acc0[c] = 0ULL; acc1[c] = 0ULL; }
        const float* w1l = w1 + lane;
        #pragma unroll 4
        for (int d = 0; d < 256; d += 2) {
            float wa = w1l[d * 32];
            float wb = w1l[d * 32 + 32];
            u64 wA = pack2(wa, wa), wB = pack2(wb, wb);
            #pragma unroll
            for (int c = 0; c < CP; c++) {
                const u64* xp = Xc + (pb + c) * 256;
                acc0[c] = ffma2(xp[d],     wA, acc0[c]);   // LDS.128 pairs with next
                acc1[c] = ffma2(xp[d + 1], wB, acc1[c]);
            }
        }
        float bb = b1v[lane];
        #pragma unroll
        for (int c = 0; c < CP; c++) {
            float lo, hi;
            unpack2(fadd2(acc0[c], acc1[c]), lo, hi);
            Hs[(wp * 4 + c) * 32 + lane] = pack2(gelu_tanh(lo + bb), gelu_tanh(hi + bb));
        }
        __syncwarp();

        // ---- phase 3: At = H @ W2 + b2; write At; next-level means in regs ----
        #pragma unroll
        for (int k = 0; k < 8; k++) {
            int d = lane + 32 * k;
            float bv = b2v[d];
            u64 acc[CP];
            #pragma unroll
            for (int c = 0; c < CP; c++) acc[c] = pack2(bv, bv);
            #pragma unroll 4
            for (int j = 0; j < 32; j += 2) {
                float wa = w2[j * 256 + d], wb = w2[(j + 1) * 256 + d];
                u64 wA = pack2(wa, wa), wB = pack2(wb, wb);
                #pragma unroll
                for (int c = 0; c < CP; c++) {
                    const u64* hp = Hs + (wp * 4 + c) * 32;
                    acc[c] = ffma2(hp[j],     wA, acc[c]);
                    acc[c] = ffma2(hp[j + 1], wB, acc[c]);
                }
            }
            float mean[CP];
            #pragma unroll
            for (int c = 0; c < CP; c++) {
                float aL, aH; unpack2(acc[c], aL, aH);
                int r2 = 2 * (pb + c);
                AtR[r2 * 256 + d]       = aL;
                AtR[(r2 + 1) * 256 + d] = aH;
                float uL, uH; unpack2(fadd2(Xc[(pb + c) * 256 + d], acc[c]), uL, uH);
                mean[c] = 0.5f * (uL + uH);
            }
            if (CP == 4) {
                Xn[(pb >> 1) * 256 + d]       = pack2(mean[0], mean[1]);
                Xn[((pb >> 1) + 1) * 256 + d] = pack2(mean[2], mean[3]);
            } else if (CP == 2) {
                Xn[(pb >> 1) * 256 + d] = pack2(mean[0], mean[1]);
            } else {
                ((float*)(Xn + (pb >> 1) * 256 + d))[pb & 1] = mean[0];
            }
        }
        __syncwarp();
    }
}

// Final single-row level (nr == 1). Row stored in even slots of Xc pair 0.
// uOut != nullptr -> also write the updated row (x + At).
__device__ __forceinline__ void mlp_final_row(
    const u64* __restrict__ Xc, float* __restrict__ Hf,
    float* __restrict__ AtR, float* __restrict__ uOut,
    const float* __restrict__ w1, const float* __restrict__ b1v,
    const float* __restrict__ w2, const float* __restrict__ b2v,
    int wp, int lane)
{
    if (wp != 0) return;
    const float* xf = (const float*)Xc;        // x[d] = xf[2d]
    float a0 = 0.f, a1 = 0.f, a2 = 0.f, a3 = 0.f;
    #pragma unroll 4
    for (int d = 0; d < 256; d += 4) {
        a0 = fmaf(xf[2 * d + 0], w1[(d + 0) * 32 + lane], a0);
        a1 = fmaf(xf[2 * d + 2], w1[(d + 1) * 32 + lane], a1);
        a2 = fmaf(xf[2 * d + 4], w1[(d + 2) * 32 + lane], a2);
        a3 = fmaf(xf[2 * d + 6], w1[(d + 3) * 32 + lane], a3);
    }
    Hf[lane] = gelu_tanh((a0 + a1) + (a2 + a3) + b1v[lane]);
    __syncwarp();
    #pragma unroll
    for (int k = 0; k < 8; k++) {
        int d = lane + 32 * k;
        float s0 = b2v[d], s1 = 0.f;
        #pragma unroll 8
        for (int j = 0; j < 32; j += 2) {
            s0 = fmaf(Hf[j],     w2[j * 256 + d],       s0);
            s1 = fmaf(Hf[j + 1], w2[(j + 1) * 256 + d], s1);
        }
        float a = s0 + s1;
        AtR[d] = a;
        if (uOut) uOut[d] = xf[2 * d] + a;
    }
}

// ---------------------------------------------------------------------------
// Levels 0..6 fused. Block = 128 Z rows = 32 level-0 pairs. 1024 blocks.
// smem: region A 32 pairs (64KB) + region B 16 pairs (32KB) + H (8KB) = 104KB.
// ---------------------------------------------------------------------------
__global__ void __launch_bounds__(256, 2) pyramid_kernel(
    const float2* __restrict__ Z2,
    const float* __restrict__ W1, const float* __restrict__ b1,
    const float* __restrict__ W2, const float* __restrict__ b2)
{
    extern __shared__ u64 sh[];
    u64* A  = sh;            // 32*256 u64
    u64* B  = sh + 8192;     // 16*256 u64
    u64* Hs = sh + 12288;    // 32*32 u64

    const int t    = threadIdx.x;
    const int lane = t & 31;
    const int wp   = t >> 5;

    // ---- fill A: pair p <-> Z rows 4p..4p+3 (pair means), pair-interleaved ----
    {
        const long long zr0 = (long long)blockIdx.x * 128;
        #pragma unroll
        for (int k = 0; k < 16; k++) {
            int task = t + 256 * k;            // 0..4095
            int pr   = task >> 7;              // 0..31
            int dh   = task & 127;             // d/2
            const float2* zp = Z2 + (zr0 + 4 * pr) * 128 + dh;
            float2 a0 = zp[0], a1 = zp[128], a2 = zp[256], a3 = zp[384];
            ((float4*)A)[pr * 128 + dh] =
                make_float4(0.5f * (a0.x + a1.x), 0.5f * (a2.x + a3.x),
                            0.5f * (a0.y + a1.y), 0.5f * (a2.y + a3.y));
        }
    }
    __syncthreads();

    float* AtBase = (float*)g_At4;
    const long long p0base = (long long)blockIdx.x * 64;  // global level-0 row base

    u64* Xc = A; u64* Xn = B;
    int np = 32;
    for (int lvl = 0; lvl < 6; lvl++) {
        const float* w1 = W1 + lvl * 8192;
        const float* v1 = b1 + lvl * 32;
        const float* w2 = W2 + lvl * 8192;
        const float* v2 = b2 + lvl * 256;
        float* AtR = AtBase + offF(lvl) + (p0base >> lvl) * 256;
        if (np == 32)      mlp_level<4>(Xc, Xn, Hs, np, AtR, w1, v1, w2, v2, wp, lane);
        else if (np == 16) mlp_level<2>(Xc, Xn, Hs, np, AtR, w1, v1, w2, v2, wp, lane);
        else               mlp_level<1>(Xc, Xn, Hs, np, AtR, w1, v1, w2, v2, wp, lane);
        __syncthreads();
        u64* tmp = Xc; Xc = Xn; Xn = tmp;
        np >>= 1;
    }
    // level 6: single row
    mlp_final_row(Xc, (float*)Hs,
                  AtBase + offF(6) + (p0base >> 6) * 256,
                  g_P6u + (p0base >> 6) * 256,
                  W1 + 6 * 8192, b1 + 6 * 32, W2 + 6 * 8192, b2 + 6 * 256,
                  wp, lane);
}

// ---------------------------------------------------------------------------
// Levels 7..13 fused. One block per batch. Input: 128 updated level-6 rows.
// ---------------------------------------------------------------------------
__global__ void __launch_bounds__(256, 2) tail_kernel(
    const float* __restrict__ W1, const float* __restrict__ b1,
    const float* __restrict__ W2, const float* __restrict__ b2)
{
    extern __shared__ u64 sh[];
    u64* A  = sh;
    u64* B  = sh + 8192;
    u64* Hs = sh + 12288;

    const int b    = blockIdx.x;
    const int t    = threadIdx.x;
    const int lane = t & 31;
    const int wp   = t >> 5;

    // fill A: level-7 pair p <-> P6u rows b*128 + 4p..4p+3 (pair means)
    {
        const float2* P2 = (const float2*)g_P6u;
        #pragma unroll
        for (int k = 0; k < 16; k++) {
            int task = t + 256 * k;
            int pr   = task >> 7;
            int dh   = task & 127;
            const float2* zp = P2 + (long long)(b * 128 + 4 * pr) * 128 + dh;
            float2 a0 = zp[0], a1 = zp[128], a2 = zp[256], a3 = zp[384];
            ((float4*)A)[pr * 128 + dh] =
                make_float4(0.5f * (a0.x + a1.x), 0.5f * (a2.x + a3.x),
                            0.5f * (a0.y + a1.y), 0.5f * (a2.y + a3.y));
        }
    }
    __syncthreads();

    float* AtBase = (float*)g_At4;

    u64* Xc = A; u64* Xn = B;
    int np = 32;
    for (int i = 0; i < 6; i++) {
        int lvl = 7 + i;
        int tt  = (lvl < 10) ? lvl : 9;
        const float* w1 = W1 + tt * 8192;
        const float* v1 = b1 + tt * 32;
        const float* w2 = W2 + tt * 8192;
        const float* v2 = b2 + tt * 256;
        float* AtR = AtBase + offF(lvl) + (long long)b * (64 >> i) * 256;
        if (np == 32)      mlp_level<4>(Xc, Xn, Hs, np, AtR, w1, v1, w2, v2, wp, lane);
        else if (np == 16) mlp_level<2>(Xc, Xn, Hs, np, AtR, w1, v1, w2, v2, wp, lane);
        else               mlp_level<1>(Xc, Xn, Hs, np, AtR, w1, v1, w2, v2, wp, lane);
        __syncthreads();
        u64* tmp = Xc; Xc = Xn; Xn = tmp;
        np >>= 1;
    }
    // level 13: single row per batch, no u output
    mlp_final_row(Xc, (float*)Hs,
                  AtBase + offF(13) + b * 256, nullptr,
                  W1 + 9 * 8192, b1 + 9 * 32, W2 + 9 * 8192, b2 + 9 * 256,
                  wp, lane);
}

// ---------------------------------------------------------------------------
// out = Z + sum over 14 levels of At[level][b, s>>(L+1), d]
// ---------------------------------------------------------------------------
__global__ void __launch_bounds__(256) final_kernel(
    const float4* __restrict__ Z4, float4* __restrict__ out4)
{
    int i   = blockIdx.x * 256 + threadIdx.x;
    int d4  = i & 63;
    int row = i >> 6;
    int b   = row >> 14;
    int s   = row & 16383;

    float4 acc = Z4[i];
    long long off4 = 0;
    int ng = 8192;
    #pragma unroll
    for (int L = 0; L < 14; L++) {
        int g = s >> (L + 1);
        float4 a = g_At4[off4 + (long long)(b * ng + g) * 64 + d4];
        acc.x += a.x; acc.y += a.y; acc.z += a.z; acc.w += a.w;
        off4 += 512LL * ng;
        ng >>= 1;
    }
    out4[i] = acc;
}

extern "C" void kernel_launch(void* const* d_in, const int* in_sizes, int n_in,
                              void* d_out, int out_size)
{
    const float* Z  = (const float*)d_in[0];
    const float* W1 = (const float*)d_in[1];
    const float* b1 = (const float*)d_in[2];
    const float* W2 = (const float*)d_in[3];
    const float* b2 = (const float*)d_in[4];

    const int SMEM = (32 + 16) * 256 * 8 + 32 * 32 * 8;   // 106496 B
    static bool attrSet = false;
    if (!attrSet) {
        cudaFuncSetAttribute(pyramid_kernel, cudaFuncAttributeMaxDynamicSharedMemorySize, SMEM);
        cudaFuncSetAttribute(tail_kernel,    cudaFuncAttributeMaxDynamicSharedMemorySize, SMEM);
        attrSet = true;
    }

    pyramid_kernel<<<1024, 256, SMEM>>>((const float2*)Z, W1, b1, W2, b2);
    tail_kernel<<<8, 256, SMEM>>>(W1, b1, W2, b2);
    final_kernel<<<32768, 256>>>((const float4*)Z, (float4*)d_out);
}

// round 7
// speedup vs baseline: 1.3448x; 1.3392x over previous
#include <cuda_runtime.h>
#include <cstdint>

// Hierarchical polarization:
//   P_0 = pairwise means of Z;  P_{L+1}[G] = mean over pair of (P_L + At_L)
//   out = Z + sum_L At_L[group(s,L)]
// setup_pack:   pre-pack weights for f32x2 inner loops.
// stage_kernel: 6 levels fused per CTA; stage1 (2048 CTAs, L0..5 from Z),
//               stage2 (32 CTAs, L6..11 from u5), stage3 (8 CTAs, L12..13 from u11).
// final_kernel: out = Z + gather over At pyramid.

typedef unsigned long long u64;

__device__ float  g_At[33554432];     // At pyramid, 14 levels, 128 MiB
__device__ float  g_u5[2048 * 256];   // updated level-5 rows
__device__ float  g_u11[32 * 256];    // updated level-11 rows
__device__ float4 g_W1p[10 * 2048];   // [t][dd=0..63][lane]: (w1[4dd..4dd+3][lane])
__device__ u64    g_W2p[10 * 4096];   // [t][j][kk*32+l]: (w2[j][l+64kk], w2[j][l+64kk+32])
__device__ u64    g_b2p[10 * 128];    // [t][kk*32+l]:    (b2[l+64kk],    b2[l+64kk+32])

__device__ __forceinline__ u64 pack2(float lo, float hi) {
    u64 r; asm("mov.b64 %0, {%1, %2};" : "=l"(r) : "f"(lo), "f"(hi)); return r;
}
__device__ __forceinline__ void unpack2(u64 v, float& lo, float& hi) {
    asm("mov.b64 {%0, %1}, %2;" : "=f"(lo), "=f"(hi) : "l"(v));
}
__device__ __forceinline__ u64 ffma2(u64 a, u64 b, u64 c) {
    u64 d; asm("fma.rn.f32x2 %0, %1, %2, %3;" : "=l"(d) : "l"(a), "l"(b), "l"(c)); return d;
}
__device__ __forceinline__ u64 fadd2(u64 a, u64 b) {
    u64 d; asm("add.rn.f32x2 %0, %1, %2;" : "=l"(d) : "l"(a), "l"(b)); return d;
}
__device__ __forceinline__ float gelu_tanh(float x) {
    // jax.nn.gelu approximate=True; tanh(u) = 1 - 2/(exp(2u)+1)
    float u = 0.7978845608028654f * (x + 0.044715f * x * x * x);
    float e = __expf(2.0f * u);
    float t = 1.0f - __fdividef(2.0f, e + 1.0f);
    return 0.5f * x * (1.0f + t);
}
__device__ __forceinline__ long long offF(int l) {   // float offset of level l in At
    return (131072LL - (131072LL >> l)) * 256LL;
}

// ---------------------------------------------------------------------------
__global__ void setup_pack(const float* __restrict__ W1, const float* __restrict__ W2,
                           const float* __restrict__ b2)
{
    int t = blockIdx.x, tid = threadIdx.x;
    const float* w1 = W1 + t * 8192;
    for (int i = tid; i < 2048; i += 256) {
        int dd = i >> 5, l = i & 31;
        g_W1p[t * 2048 + i] = make_float4(
            w1[(4 * dd + 0) * 32 + l], w1[(4 * dd + 1) * 32 + l],
            w1[(4 * dd + 2) * 32 + l], w1[(4 * dd + 3) * 32 + l]);
    }
    const float* w2 = W2 + t * 8192;
    for (int i = tid; i < 4096; i += 256) {
        int j = i >> 7, r = i & 127, kk = r >> 5, l = r & 31;
        g_W2p[t * 4096 + i] = pack2(w2[j * 256 + l + 64 * kk],
                                    w2[j * 256 + l + 64 * kk + 32]);
    }
    if (tid < 128) {
        int kk = tid >> 5, l = tid & 31;
        g_b2p[t * 128 + tid] = pack2(b2[t * 256 + l + 64 * kk],
                                     b2[t * 256 + l + 64 * kk + 32]);
    }
}

// ---------------------------------------------------------------------------
// Phase 1: H rows rb..rb+CP-1 = gelu(X @ W1 + b1). f32x2 over adjacent d's.
// X loads are LDS.128 broadcasts; W loads are coalesced LDG.128 (L1-resident).
// ---------------------------------------------------------------------------
template<int CP>
__device__ __forceinline__ void phase1_chunk(
    const float* __restrict__ Xc, u64* __restrict__ Hd, int rb,
    const float4* __restrict__ W1p, const float* __restrict__ b1v, int lane)
{
    u64 aA[CP], aB[CP];
    #pragma unroll
    for (int c = 0; c < CP; c++) { aA[c] = 0ULL; aB[c] = 0ULL; }
    const float4* X4 = (const float4*)Xc;
    #pragma unroll 8
    for (int dd = 0; dd < 64; dd++) {
        union { float4 f; u64 u[2]; } w; w.f = W1p[dd * 32 + lane];
        #pragma unroll
        for (int c = 0; c < CP; c++) {
            union { float4 f; u64 u[2]; } x; x.f = X4[(rb + c) * 64 + dd];
            aA[c] = ffma2(x.u[0], w.u[0], aA[c]);
            aB[c] = ffma2(x.u[1], w.u[1], aB[c]);
        }
    }
    float bb = b1v[lane];
    #pragma unroll
    for (int c = 0; c < CP; c++) {
        float lo, hi; unpack2(fadd2(aA[c], aB[c]), lo, hi);
        float h = gelu_tanh(lo + hi + bb);
        Hd[(rb + c) * 32 + lane] = pack2(h, h);
    }
}

// ---------------------------------------------------------------------------
// Phase 3 for a row pair: At = H @ W2 + b2 (stored), Xn[pp] = pair mean of x+At.
// f32x2 packs output dims (d, d+32); H reads are LDS.64 broadcasts.
// ---------------------------------------------------------------------------
__device__ __forceinline__ void phase3_pair(
    const float* __restrict__ Xc, float* __restrict__ Xn, const u64* __restrict__ Hd,
    int pp, float* __restrict__ AtB,
    const u64* __restrict__ W2p, const u64* __restrict__ b2p, int lane)
{
    const int r0 = 2 * pp, r1 = r0 + 1;
    u64 a0[4], a1[4];
    #pragma unroll
    for (int kk = 0; kk < 4; kk++) { u64 b = b2p[kk * 32 + lane]; a0[kk] = b; a1[kk] = b; }
    const u64* H0 = Hd + r0 * 32;
    const u64* H1 = Hd + r1 * 32;
    #pragma unroll 4
    for (int j = 0; j < 32; j++) {
        u64 h0 = H0[j], h1 = H1[j];
        const u64* wr = W2p + j * 128 + lane;
        #pragma unroll
        for (int kk = 0; kk < 4; kk++) {
            u64 w = wr[kk * 32];
            a0[kk] = ffma2(h0, w, a0[kk]);
            a1[kk] = ffma2(h1, w, a1[kk]);
        }
    }
    #pragma unroll
    for (int kk = 0; kk < 4; kk++) {
        int da = lane + 64 * kk, db = da + 32;
        float p0a, p0b, p1a, p1b;
        unpack2(a0[kk], p0a, p0b); unpack2(a1[kk], p1a, p1b);
        AtB[r0 * 256 + da] = p0a; AtB[r0 * 256 + db] = p0b;
        AtB[r1 * 256 + da] = p1a; AtB[r1 * 256 + db] = p1b;
        Xn[pp * 256 + da] = 0.5f * ((Xc[r0 * 256 + da] + p0a) + (Xc[r1 * 256 + da] + p1a));
        Xn[pp * 256 + db] = 0.5f * ((Xc[r0 * 256 + db] + p0b) + (Xc[r1 * 256 + db] + p1b));
    }
}

// Last level of a stage (nr == 1): At + optional updated row (x + At) to global.
__device__ __forceinline__ void final_row(
    const float* __restrict__ Xc, const u64* __restrict__ Hd,
    float* __restrict__ AtB, float* __restrict__ uOut,
    const u64* __restrict__ W2p, const u64* __restrict__ b2p, int lane)
{
    u64 a[4];
    #pragma unroll
    for (int kk = 0; kk < 4; kk++) a[kk] = b2p[kk * 32 + lane];
    #pragma unroll 4
    for (int j = 0; j < 32; j++) {
        u64 h = Hd[j];
        const u64* wr = W2p + j * 128 + lane;
        #pragma unroll
        for (int kk = 0; kk < 4; kk++) a[kk] = ffma2(h, wr[kk * 32], a[kk]);
    }
    #pragma unroll
    for (int kk = 0; kk < 4; kk++) {
        int da = lane + 64 * kk, db = da + 32;
        float pa, pb; unpack2(a[kk], pa, pb);
        AtB[da] = pa; AtB[db] = pb;
        if (uOut) { uOut[da] = Xc[da] + pa; uOut[db] = Xc[db] + pb; }
    }
}

// ---------------------------------------------------------------------------
// Generic stage: CTA takes nIn input rows, entry X = pair means, then nLev
// levels of (MLP -> At -> pair means). src: 0=Z, 1=g_u5, 2=g_u11.
// Smem: Xa 32KB | Xb 16KB | Hd 8KB = 56KB -> 4 CTAs/SM.
// ---------------------------------------------------------------------------
__global__ void __launch_bounds__(256, 4) stage_kernel(
    const float4* __restrict__ Z4, int src, int nIn, int l0, int nLev,
    const float* __restrict__ b1all)
{
    extern __shared__ float sm[];
    float* Xa = sm;
    float* Xb = sm + 8192;
    u64*   Hd = (u64*)(sm + 12288);

    const int bi   = blockIdx.x;
    const int tid  = threadIdx.x;
    const int lane = tid & 31;
    const int wp   = tid >> 5;

    const float4* in4 =
        (src == 0) ? (Z4 + (long long)bi * nIn * 64)
                   : ((src == 1) ? ((const float4*)g_u5 + (long long)bi * nIn * 64)
                                 : ((const float4*)g_u11 + (long long)bi * nIn * 64));
    float* uOut = (src == 0) ? (g_u5 + bi * 256)
                             : ((src == 1) ? (g_u11 + bi * 256) : nullptr);

    // ---- entry: X = pair means of input rows ----
    int nr = nIn >> 1;
    for (int i = tid; i < nr * 64; i += 256) {
        int r = i >> 6, c = i & 63;
        float4 a = in4[(2 * r) * 64 + c];
        float4 b = in4[(2 * r + 1) * 64 + c];
        ((float4*)Xa)[i] = make_float4(0.5f * (a.x + b.x), 0.5f * (a.y + b.y),
                                       0.5f * (a.z + b.z), 0.5f * (a.w + b.w));
    }
    __syncthreads();

    float* Xc = Xa; float* Xn = Xb;
    for (int i = 0; i < nLev; i++) {
        int l  = l0 + i;
        int tt = (l < 10) ? l : 9;
        const float4* W1p = g_W1p + tt * 2048;
        const float*  b1v = b1all + tt * 32;
        const u64*    W2p = g_W2p + tt * 4096;
        const u64*    b2p = g_b2p + tt * 128;
        float* AtB = g_At + offF(l) + (long long)bi * nr * 256;

        // phase 1 -> Hd
        if (nr >= 4) {
            int rb = 4 * wp;
            if (rb < nr) phase1_chunk<4>(Xc, Hd, rb, W1p, b1v, lane);
        } else if (nr == 2) {
            if (wp == 0) phase1_chunk<2>(Xc, Hd, 0, W1p, b1v, lane);
        } else {
            if (wp == 0) phase1_chunk<1>(Xc, Hd, 0, W1p, b1v, lane);
        }
        __syncthreads();

        if (nr == 1) {
            if (wp == 0) final_row(Xc, Hd, AtB, uOut, W2p, b2p, lane);
            __syncthreads();
        } else {
            int np = nr >> 1;
            for (int pp = wp; pp < np; pp += 8)
                phase3_pair(Xc, Xn, Hd, pp, AtB, W2p, b2p, lane);
            __syncthreads();
        }
        float* t2 = Xc; Xc = Xn; Xn = t2;
        nr >>= 1;
    }
}

// ---------------------------------------------------------------------------
// out = Z + sum over 14 levels of At[level][b, s>>(L+1), d]
// ---------------------------------------------------------------------------
__global__ void __launch_bounds__(256) final_kernel(
    const float4* __restrict__ Z4, float4* __restrict__ out4)
{
    int i   = blockIdx.x * 256 + threadIdx.x;
    int d4  = i & 63;
    int row = i >> 6;
    int b   = row >> 14;
    int s   = row & 16383;

    const float4* At4 = (const float4*)g_At;
    float4 acc = Z4[i];
    long long off4 = 0;
    int ng = 8192;
    #pragma unroll
    for (int L = 0; L < 14; L++) {
        int g = s >> (L + 1);
        float4 a = At4[off4 + (long long)(b * ng + g) * 64 + d4];
        acc.x += a.x; acc.y += a.y; acc.z += a.z; acc.w += a.w;
        off4 += 512LL * ng;
        ng >>= 1;
    }
    out4[i] = acc;
}

extern "C" void kernel_launch(void* const* d_in, const int* in_sizes, int n_in,
                              void* d_out, int out_size)
{
    const float* Z  = (const float*)d_in[0];
    const float* W1 = (const float*)d_in[1];
    const float* b1 = (const float*)d_in[2];
    const float* W2 = (const float*)d_in[3];
    const float* b2 = (const float*)d_in[4];

    const int SMEM = 57344;   // 32KB Xa + 16KB Xb + 8KB Hd
    cudaFuncSetAttribute(stage_kernel, cudaFuncAttributeMaxDynamicSharedMemorySize, SMEM);

    setup_pack<<<10, 256>>>(W1, W2, b2);
    stage_kernel<<<2048, 256, SMEM>>>((const float4*)Z, 0, 64, 0, 6, b1);   // L0..5
    stage_kernel<<<32,   256, SMEM>>>((const float4*)Z, 1, 64, 6, 6, b1);   // L6..11
    stage_kernel<<<8,    256, SMEM>>>((const float4*)Z, 2, 4, 12, 2, b1);   // L12..13
    final_kernel<<<32768, 256>>>((const float4*)Z, (float4*)d_out);
}